// round 7
// baseline (speedup 1.0000x reference)
#include <cuda_runtime.h>
#include <cuda_fp16.h>
#include <cstdint>

// NTXentLoss N=8192, D=128 fp32.
// loss = mean_i( log(sum_{j!=i} exp(10*cos(i,j))) - 10*cos(i, i^4096) )
// int8 tensor path: z quantized per-row to s8, sim via mma.sync.m16n8k32.s8 (s32 acc),
// rescaled in epilogue by per-row scales; streaming exp-sum (logits in [-10,10]).
// Positive-pair term exact fp32 (tiny separate kernel, pair-symmetric).

#define NN 8192
#define DD 128
#define ROWB 144                 // padded smem row: 128 int8 + 16 pad
#define TILEB (128 * ROWB)       // 18432 B per 128x128 int8 tile
#define EXK 14.4269504088896340736f   // 10 * log2(e)

__device__ float    g_zf[NN * DD];     // normalized fp32 (exact pos term)
__device__ uint32_t g_q[NN * 32];      // int8 quantized z, 4 packed per u32
__device__ float    g_si[NN];          // per-row scale: max|z_row| / 127
__device__ float    g_sum2[2][NN];     // exp-sum partials per column half

__device__ __forceinline__ uint32_t smem_u32(const void* p) {
    return (uint32_t)__cvta_generic_to_shared(p);
}
__device__ __forceinline__ void cp16(uint32_t dst, const void* src) {
    asm volatile("cp.async.cg.shared.global [%0], [%1], 16;\n" :: "r"(dst), "l"(src));
}
__device__ __forceinline__ float ex2f(float x) {
    float r; asm("ex2.approx.f32 %0, %1;" : "=f"(r) : "f"(x)); return r;
}
__device__ __forceinline__ void ldsm_x4(uint32_t a, uint32_t r[4]) {
    asm volatile("ldmatrix.sync.aligned.m8n8.x4.shared.b16 {%0,%1,%2,%3}, [%4];"
                 : "=r"(r[0]), "=r"(r[1]), "=r"(r[2]), "=r"(r[3]) : "r"(a));
}
__device__ __forceinline__ void imma16832(int c[4], const uint32_t a[4],
                                          const uint32_t b[2]) {
    asm volatile(
        "mma.sync.aligned.m16n8k32.row.col.s32.s8.s8.s32 "
        "{%0,%1,%2,%3}, {%4,%5,%6,%7}, {%8,%9}, {%0,%1,%2,%3};"
        : "+r"(c[0]), "+r"(c[1]), "+r"(c[2]), "+r"(c[3])
        : "r"(a[0]), "r"(a[1]), "r"(a[2]), "r"(a[3]), "r"(b[0]), "r"(b[1]));
}

// ---------------------------------------------------------------------------
// Phase 1: warp-per-row normalize + int8 quantize. Also zeroes out[0].
// ---------------------------------------------------------------------------
__global__ void __launch_bounds__(256) nt_normalize(const float* __restrict__ x,
                                                    float* __restrict__ out) {
    const int lane = threadIdx.x & 31;
    const int row = blockIdx.x * 8 + (threadIdx.x >> 5);
    const float4 v = reinterpret_cast<const float4*>(x)[row * 32 + lane];
    float ss = v.x * v.x + v.y * v.y + v.z * v.z + v.w * v.w;
    float mv = fmaxf(fmaxf(fabsf(v.x), fabsf(v.y)), fmaxf(fabsf(v.z), fabsf(v.w)));
#pragma unroll
    for (int o = 16; o; o >>= 1) {
        ss += __shfl_xor_sync(0xffffffffu, ss, o);
        mv = fmaxf(mv, __shfl_xor_sync(0xffffffffu, mv, o));
    }
    const float inv = 1.0f / fmaxf(sqrtf(ss), 1e-8f);
    float4 z; z.x = v.x * inv; z.y = v.y * inv; z.z = v.z * inv; z.w = v.w * inv;
    reinterpret_cast<float4*>(g_zf)[row * 32 + lane] = z;
    const float m = fmaxf(mv * inv, 1e-8f);
    const float qs = 127.0f / m;
    const int q0 = __float2int_rn(z.x * qs), q1 = __float2int_rn(z.y * qs);
    const int q2 = __float2int_rn(z.z * qs), q3 = __float2int_rn(z.w * qs);
    g_q[row * 32 + lane] = (uint32_t)(q0 & 255) | ((uint32_t)(q1 & 255) << 8)
                         | ((uint32_t)(q2 & 255) << 16) | ((uint32_t)(q3 & 255) << 24);
    if (lane == 0) g_si[row] = m * (1.0f / 127.0f);
    if (row == 0 && lane == 0) out[0] = 0.0f;
}

// Load one [128 samples][128B] int8 tile into padded smem rows.
__device__ __forceinline__ void load_tile(uint32_t sdst, int sbase, int tid) {
#pragma unroll
    for (int i = 0; i < 4; ++i) {          // 1024 x 16B / 256 threads
        const int f = tid + (i << 8);
        const int row = f >> 3, ck = f & 7;
        cp16(sdst + row * ROWB + (ck << 4),
             (const char*)g_q + (((size_t)(sbase + row)) << 7) + (ck << 4));
    }
}

// ---------------------------------------------------------------------------
// Phase 2: int8 GEMM + streaming exp-sum. Grid 128 = 64 row-blocks x 2 halves.
// 8 warps as 2(M) x 4(N); warp tile 64x32; K=128 resident in smem.
// ---------------------------------------------------------------------------
__global__ void __launch_bounds__(256) nt_main() {
    extern __shared__ char sm[];
    __shared__ float s_red[128];

    const int tid = threadIdx.x, wid = tid >> 5, lane = tid & 31;
    const int wM = wid >> 2, wN = wid & 3;
    const int rowBase = (blockIdx.x >> 1) * 128;
    const int ch = blockIdx.x & 1;
    const int colHalf = ch * 4096;
    const uint32_t smem0 = smem_u32(sm);
    const uint32_t bBase[2] = {smem0 + TILEB, smem0 + 2 * TILEB};
    float* const scolP[2] = {(float*)(sm + 3 * TILEB), (float*)(sm + 3 * TILEB + 512)};
    const uint32_t scolA[2] = {smem0 + 3 * TILEB, smem0 + 3 * TILEB + 512};

    load_tile(smem0, rowBase, tid);
    load_tile(bBase[0], colHalf, tid);
    if (tid < 32) cp16(scolA[0] + (tid << 4), g_si + colHalf + (tid << 2));
    asm volatile("cp.async.commit_group;\n");

    if (tid < 128) s_red[tid] = 0.0f;

    // ldmatrix per-lane byte offsets (s8 fragments via b16 ldmatrix):
    const uint32_t aLane = (uint32_t)((wM * 64 + (lane & 15)) * ROWB + ((lane >> 4) << 4));
    const uint32_t bLane = (uint32_t)((wN * 32 + (lane & 15)) * ROWB + ((lane >> 4) << 4));

    const int thRow0 = rowBase + wM * 64 + (lane >> 2);  // + mf*16 + rh*8
    const int thCol0 = wN * 32 + ((lane & 3) << 1);      // + nf*8 + j (tile-local)

    float rowfac[8];
#pragma unroll
    for (int i = 0; i < 8; ++i)
        rowfac[i] = EXK * g_si[thRow0 + (i >> 1) * 16 + (i & 1) * 8];

    float sE[8];
#pragma unroll
    for (int i = 0; i < 8; ++i) sE[i] = 0.0f;

    for (int t = 0; t < 32; ++t) {
        asm volatile("cp.async.wait_group 0;\n" ::: "memory");
        __syncthreads();
        if (t + 1 < 32) {
            load_tile(bBase[(t + 1) & 1], colHalf + (t + 1) * 128, tid);
            if (tid < 32)
                cp16(scolA[(t + 1) & 1] + (tid << 4), g_si + colHalf + (t + 1) * 128 + (tid << 2));
            asm volatile("cp.async.commit_group;\n");
        }
        const uint32_t bb = bBase[t & 1];

        int c[4][4][4];
#pragma unroll
        for (int mf = 0; mf < 4; ++mf)
#pragma unroll
            for (int nf = 0; nf < 4; ++nf)
#pragma unroll
                for (int r = 0; r < 4; ++r) c[mf][nf][r] = 0;

#pragma unroll
        for (int ks = 0; ks < 4; ++ks) {
            uint32_t a[4][4], b[4][2];
#pragma unroll
            for (int mf = 0; mf < 4; ++mf)
                ldsm_x4(smem0 + aLane + (uint32_t)(mf * 16 * ROWB) + (ks << 5), a[mf]);
#pragma unroll
            for (int np = 0; np < 2; ++np) {
                uint32_t r4[4];
                ldsm_x4(bb + bLane + (uint32_t)(np * 16 * ROWB) + (ks << 5), r4);
                b[2 * np][0] = r4[0]; b[2 * np][1] = r4[2];
                b[2 * np + 1][0] = r4[1]; b[2 * np + 1][1] = r4[3];
            }
#pragma unroll
            for (int mf = 0; mf < 4; ++mf)
#pragma unroll
                for (int nf = 0; nf < 4; ++nf)
                    imma16832(c[mf][nf], a[mf], b[nf]);
        }

        // Epilogue: logit(log2-domain) = acc * (EXK*si_row) * si_col; exp-sum.
        float2 cf[4];
        float* scol = scolP[t & 1];
#pragma unroll
        for (int nf = 0; nf < 4; ++nf)
            cf[nf] = *reinterpret_cast<float2*>(scol + thCol0 + nf * 8);

        const int cb = colHalf + t * 128;
        if (cb == rowBase) {            // diagonal tile: mask col==row
#pragma unroll
            for (int mf = 0; mf < 4; ++mf)
#pragma unroll
                for (int nf = 0; nf < 4; ++nf)
#pragma unroll
                    for (int r = 0; r < 4; ++r) {
                        const int row = thRow0 + mf * 16 + ((r >> 1) << 3);
                        const int col = cb + thCol0 + nf * 8 + (r & 1);
                        const float v = (float)c[mf][nf][r] * rowfac[mf * 2 + (r >> 1)]
                                        * ((r & 1) ? cf[nf].y : cf[nf].x);
                        sE[mf * 2 + (r >> 1)] += (col == row) ? 0.0f : ex2f(v);
                    }
        } else {
#pragma unroll
            for (int mf = 0; mf < 4; ++mf)
#pragma unroll
                for (int nf = 0; nf < 4; ++nf)
#pragma unroll
                    for (int r = 0; r < 4; ++r) {
                        const float v = (float)c[mf][nf][r] * rowfac[mf * 2 + (r >> 1)]
                                        * ((r & 1) ? cf[nf].y : cf[nf].x);
                        sE[mf * 2 + (r >> 1)] += ex2f(v);
                    }
        }
    }

    // Reduce: lanes 4q..4q+3 share rows -> shfl; smem atomics; plain global store.
#pragma unroll
    for (int i = 0; i < 8; ++i) {
        sE[i] += __shfl_xor_sync(0xffffffffu, sE[i], 1);
        sE[i] += __shfl_xor_sync(0xffffffffu, sE[i], 2);
    }
    __syncthreads();
    if ((lane & 3) == 0) {
        const int lr0 = wM * 64 + (lane >> 2);
#pragma unroll
        for (int i = 0; i < 8; ++i)
            atomicAdd(&s_red[lr0 + (i >> 1) * 16 + (i & 1) * 8], sE[i]);
    }
    __syncthreads();
    if (tid < 128) g_sum2[ch][rowBase + tid] = s_red[tid];
}

// ---------------------------------------------------------------------------
// Phase 3: pos(i)=pos(i^4096) computed once per pair in exact fp32; loss mean.
// ---------------------------------------------------------------------------
__global__ void __launch_bounds__(256) nt_final(float* __restrict__ out) {
    const int w = threadIdx.x >> 5, lane = threadIdx.x & 31;
    const int p = (blockIdx.x << 3) + w;          // pair id 0..4095
    const int rA = p, rB = p + NN / 2;
    const float4 a = reinterpret_cast<const float4*>(g_zf)[rA * 32 + lane];
    const float4 b = reinterpret_cast<const float4*>(g_zf)[rB * 32 + lane];
    float d = a.x * b.x + a.y * b.y + a.z * b.z + a.w * b.w;
#pragma unroll
    for (int o = 16; o; o >>= 1) d += __shfl_xor_sync(0xffffffffu, d, o);
    __shared__ float ws[8];
    if (lane == 0) {
        const float sA = g_sum2[0][rA] + g_sum2[1][rA];
        const float sB = g_sum2[0][rB] + g_sum2[1][rB];
        ws[w] = __logf(sA) + __logf(sB) - 20.0f * d;
    }
    __syncthreads();
    if (threadIdx.x == 0) {
        float s = 0.0f;
#pragma unroll
        for (int i = 0; i < 8; ++i) s += ws[i];
        atomicAdd(out, s * (1.0f / NN));
    }
}

// ---------------------------------------------------------------------------
extern "C" void kernel_launch(void* const* d_in, const int* in_sizes, int n_in,
                              void* d_out, int out_size) {
    (void)in_sizes; (void)n_in; (void)out_size;
    const float* x = (const float*)d_in[0];
    float* out = (float*)d_out;

    nt_normalize<<<NN / 8, 256>>>(x, out);

    const int smem = 3 * TILEB + 1024;   // 56320 B
    cudaFuncSetAttribute(nt_main, cudaFuncAttributeMaxDynamicSharedMemorySize, smem);
    nt_main<<<128, 256, smem>>>();

    nt_final<<<NN / 16, 256>>>(out);
}

// round 9
// speedup vs baseline: 3.4993x; 3.4993x over previous
#include <cuda_runtime.h>
#include <cuda_fp16.h>
#include <cstdint>

// NTXentLoss N=8192, D=128 fp32.
// loss = mean_i( log(sum_{j!=i} exp(10*cos(i,j))) - 10*cos(i, i^4096) )
// fp16 HMMA path (mma.sync.m16n8k16), SYMMETRIC: only upper-triangle block tiles
// computed; each off-diagonal tile contributes row-sums (block I) AND col-sums
// (block J) of exp. Logits bounded in [-10,10] -> streaming exp-sum, no max shift.
// Positive-pair term exact fp32 (pair-symmetric tiny kernel).

#define NN 8192
#define DD 128
#define ROWB 272               // padded smem row: 256 B (128 halves) + 16 pad
#define TILEB (128 * ROWB)     // 34816 B per 128x128 fp16 tile
#define EXK 14.4269504088896340736f   // 10 * log2(e)

__device__ float  g_zf[NN * DD];       // normalized fp32 (exact pos term)
__device__ __half g_h[NN * DD];        // normalized fp16 [n][k]
__device__ float  g_sumE[NN];          // exp-sum accumulators

__device__ __forceinline__ uint32_t smem_u32(const void* p) {
    return (uint32_t)__cvta_generic_to_shared(p);
}
__device__ __forceinline__ void cp16(uint32_t dst, const void* src) {
    asm volatile("cp.async.cg.shared.global [%0], [%1], 16;\n" :: "r"(dst), "l"(src));
}
__device__ __forceinline__ float ex2f(float x) {
    float r; asm("ex2.approx.f32 %0, %1;" : "=f"(r) : "f"(x)); return r;
}
__device__ __forceinline__ void ldsm_x4(uint32_t a, uint32_t r[4]) {
    asm volatile("ldmatrix.sync.aligned.m8n8.x4.shared.b16 {%0,%1,%2,%3}, [%4];"
                 : "=r"(r[0]), "=r"(r[1]), "=r"(r[2]), "=r"(r[3]) : "r"(a));
}
__device__ __forceinline__ void mma16816(float c[4], const uint32_t a[4],
                                         const uint32_t b[2]) {
    asm volatile(
        "mma.sync.aligned.m16n8k16.row.col.f32.f16.f16.f32 "
        "{%0,%1,%2,%3}, {%4,%5,%6,%7}, {%8,%9}, {%0,%1,%2,%3};"
        : "+f"(c[0]), "+f"(c[1]), "+f"(c[2]), "+f"(c[3])
        : "r"(a[0]), "r"(a[1]), "r"(a[2]), "r"(a[3]), "r"(b[0]), "r"(b[1]));
}

// ---------------------------------------------------------------------------
// Phase 1: warp-per-row normalize -> fp32 + fp16; zeroes g_sumE and out[0].
// ---------------------------------------------------------------------------
__global__ void __launch_bounds__(256) nt_normalize(const float* __restrict__ x,
                                                    float* __restrict__ out) {
    const int lane = threadIdx.x & 31;
    const int row = blockIdx.x * 8 + (threadIdx.x >> 5);
    const float4 v = reinterpret_cast<const float4*>(x)[row * 32 + lane];
    float ss = v.x * v.x + v.y * v.y + v.z * v.z + v.w * v.w;
#pragma unroll
    for (int o = 16; o; o >>= 1) ss += __shfl_xor_sync(0xffffffffu, ss, o);
    const float inv = 1.0f / fmaxf(sqrtf(ss), 1e-8f);
    float4 z; z.x = v.x * inv; z.y = v.y * inv; z.z = v.z * inv; z.w = v.w * inv;
    reinterpret_cast<float4*>(g_zf)[row * 32 + lane] = z;
    __half2* hp = reinterpret_cast<__half2*>(g_h) + row * 64 + lane * 2;
    hp[0] = __floats2half2_rn(z.x, z.y);
    hp[1] = __floats2half2_rn(z.z, z.w);
    if (lane == 0) g_sumE[row] = 0.0f;
    if (row == 0 && lane == 0) out[0] = 0.0f;
}

// Load one [128 samples][128 halves] tile into padded smem (272B rows).
__device__ __forceinline__ void load_tile(uint32_t sdst, int sbase, int tid) {
#pragma unroll
    for (int i = 0; i < 8; ++i) {          // 2048 x 16B / 256 threads
        const int f = tid + (i << 8);
        const int row = f >> 4, kb = f & 15;
        cp16(sdst + row * ROWB + (kb << 4),
             (const char*)g_h + ((size_t)(sbase + row) << 8) + (kb << 4));
    }
}

// ---------------------------------------------------------------------------
// Phase 2: one upper-triangle 128x128 tile per CTA. Grid 2080.
// 8 warps 2(M) x 4(N), warp tile 64x32, K=128 single pass.
// ---------------------------------------------------------------------------
__global__ void __launch_bounds__(256, 2) nt_main() {
    extern __shared__ char sm[];
    __shared__ float s_rowP[4][128];   // per-wN row partials
    __shared__ float s_colP[2][128];   // per-wM col partials

    // decode triangular (I, J), J >= I
    int idx = blockIdx.x, I = 0;
    while (idx >= 64 - I) { idx -= 64 - I; ++I; }
    const int J = I + idx;
    const bool diag = (I == J);

    const int tid = threadIdx.x, wid = tid >> 5, lane = tid & 31;
    const int wM = wid >> 2, wN = wid & 3;
    const int rowBase = I * 128, colBase = J * 128;
    const uint32_t aBase = smem_u32(sm);
    const uint32_t bBase = diag ? aBase : (aBase + TILEB);

    load_tile(aBase, rowBase, tid);
    if (!diag) load_tile(bBase, colBase, tid);
    asm volatile("cp.async.commit_group;\n");

    // ldmatrix per-lane byte offsets (validated mapping from the fp16 kernel):
    const uint32_t aLane = (uint32_t)((wM * 64 + (lane & 15)) * ROWB + ((lane >> 4) << 4));
    const uint32_t bLane = (uint32_t)((wN * 32 + ((lane >> 4) << 3) + (lane & 7)) * ROWB
                                      + (((lane >> 3) & 1) << 4));

    const int thRow0 = rowBase + wM * 64 + (lane >> 2);  // + mf*16 + rh*8
    const int thCol0 = wN * 32 + ((lane & 3) << 1);      // + nf*8 + b (tile-local)

    float c[4][4][4];
#pragma unroll
    for (int mf = 0; mf < 4; ++mf)
#pragma unroll
        for (int nf = 0; nf < 4; ++nf)
#pragma unroll
            for (int r = 0; r < 4; ++r) c[mf][nf][r] = 0.0f;

    asm volatile("cp.async.wait_group 0;\n" ::: "memory");
    __syncthreads();

#pragma unroll
    for (int ks = 0; ks < 8; ++ks) {
        uint32_t a[4][4], b[4][2];
#pragma unroll
        for (int mf = 0; mf < 4; ++mf)
            ldsm_x4(aBase + aLane + (uint32_t)(mf * 16 * ROWB) + (ks << 5), a[mf]);
#pragma unroll
        for (int np = 0; np < 2; ++np) {
            uint32_t r4[4];
            ldsm_x4(bBase + bLane + (uint32_t)(np * 16 * ROWB) + (ks << 5), r4);
            b[2 * np][0] = r4[0]; b[2 * np][1] = r4[1];
            b[2 * np + 1][0] = r4[2]; b[2 * np + 1][1] = r4[3];
        }
#pragma unroll
        for (int mf = 0; mf < 4; ++mf)
#pragma unroll
            for (int nf = 0; nf < 4; ++nf)
                mma16816(c[mf][nf], a[mf], b[nf]);
    }

    // Epilogue: e = exp(10*cos); accumulate row sums AND col sums.
    float sE[8], cS[8];
#pragma unroll
    for (int i = 0; i < 8; ++i) { sE[i] = 0.0f; cS[i] = 0.0f; }

    if (diag) {
#pragma unroll
        for (int mf = 0; mf < 4; ++mf)
#pragma unroll
            for (int nf = 0; nf < 4; ++nf)
#pragma unroll
                for (int r = 0; r < 4; ++r) {
                    const int row = thRow0 + mf * 16 + ((r >> 1) << 3);
                    const int col = colBase + thCol0 + nf * 8 + (r & 1);
                    const float e = (col == row) ? 0.0f : ex2f(c[mf][nf][r] * EXK);
                    sE[mf * 2 + (r >> 1)] += e;
                }
    } else {
#pragma unroll
        for (int mf = 0; mf < 4; ++mf)
#pragma unroll
            for (int nf = 0; nf < 4; ++nf)
#pragma unroll
                for (int r = 0; r < 4; ++r) {
                    const float e = ex2f(c[mf][nf][r] * EXK);
                    sE[mf * 2 + (r >> 1)] += e;
                    cS[nf * 2 + (r & 1)] += e;
                }
    }

    // Row reduce: lanes 4q..4q+3 share rows.
#pragma unroll
    for (int i = 0; i < 8; ++i) {
        sE[i] += __shfl_xor_sync(0xffffffffu, sE[i], 1);
        sE[i] += __shfl_xor_sync(0xffffffffu, sE[i], 2);
    }
    // Col reduce: lanes differing in lane>>2 share columns.
#pragma unroll
    for (int i = 0; i < 8; ++i) {
        cS[i] += __shfl_xor_sync(0xffffffffu, cS[i], 4);
        cS[i] += __shfl_xor_sync(0xffffffffu, cS[i], 8);
        cS[i] += __shfl_xor_sync(0xffffffffu, cS[i], 16);
    }

    if ((lane & 3) == 0) {
        const int r0 = wM * 64 + (lane >> 2);
#pragma unroll
        for (int i = 0; i < 8; ++i)
            s_rowP[wN][r0 + (i >> 1) * 16 + (i & 1) * 8] = sE[i];
    }
    if (lane < 4) {
#pragma unroll
        for (int i = 0; i < 8; ++i)
            s_colP[wM][wN * 32 + (i >> 1) * 8 + lane * 2 + (i & 1)] = cS[i];
    }
    __syncthreads();

    if (tid < 128) {
        const float rs = s_rowP[0][tid] + s_rowP[1][tid] + s_rowP[2][tid] + s_rowP[3][tid];
        atomicAdd(&g_sumE[rowBase + tid], rs);
        if (!diag) {
            const float cs = s_colP[0][tid] + s_colP[1][tid];
            atomicAdd(&g_sumE[colBase + tid], cs);
        }
    }
}

// ---------------------------------------------------------------------------
// Phase 3: pos(i) = pos(i+4096) exact fp32, once per pair; loss mean.
// ---------------------------------------------------------------------------
__global__ void __launch_bounds__(256) nt_final(float* __restrict__ out) {
    const int w = threadIdx.x >> 5, lane = threadIdx.x & 31;
    const int p = (blockIdx.x << 3) + w;          // pair id 0..4095
    const int rA = p, rB = p + NN / 2;
    const float4 a = reinterpret_cast<const float4*>(g_zf)[rA * 32 + lane];
    const float4 b = reinterpret_cast<const float4*>(g_zf)[rB * 32 + lane];
    float d = a.x * b.x + a.y * b.y + a.z * b.z + a.w * b.w;
#pragma unroll
    for (int o = 16; o; o >>= 1) d += __shfl_xor_sync(0xffffffffu, d, o);
    __shared__ float ws[8];
    if (lane == 0)
        ws[w] = __logf(g_sumE[rA]) + __logf(g_sumE[rB]) - 20.0f * d;
    __syncthreads();
    if (threadIdx.x == 0) {
        float s = 0.0f;
#pragma unroll
        for (int i = 0; i < 8; ++i) s += ws[i];
        atomicAdd(out, s * (1.0f / NN));
    }
}

// ---------------------------------------------------------------------------
extern "C" void kernel_launch(void* const* d_in, const int* in_sizes, int n_in,
                              void* d_out, int out_size) {
    (void)in_sizes; (void)n_in; (void)out_size;
    const float* x = (const float*)d_in[0];
    float* out = (float*)d_out;

    nt_normalize<<<NN / 8, 256>>>(x, out);

    const int smem = 2 * TILEB;   // 69632 B
    cudaFuncSetAttribute(nt_main, cudaFuncAttributeMaxDynamicSharedMemorySize, smem);
    nt_main<<<2080, 256, smem>>>();

    nt_final<<<NN / 16, 256>>>(out);
}

// round 10
// speedup vs baseline: 4.2299x; 1.2088x over previous
#include <cuda_runtime.h>
#include <cuda_fp16.h>
#include <cstdint>

// NTXentLoss N=8192, D=128 fp32.
// loss = mean_i( log(sum_{j!=i} exp(10*cos(i,j))) - 10*cos(i, i^4096) )
// fp16 HMMA (mma.sync.m16n8k16), symmetric upper-triangle tiles (2080 of 128x128).
// Grid 296 persistent-ish CTAs; each owns a contiguous chunk of triangle tiles:
// A tile reused across the row, next B tile prefetched under current MMA.
// Streaming exp-sum (logits bounded in [-10,10]); pos term exact fp32.

#define NN 8192
#define DD 128
#define ROWB 272               // padded smem row: 256 B (128 halves) + 16 pad
#define TILEB (128 * ROWB)     // 34816 B per 128x128 fp16 tile
#define NT 2080                // 64*65/2 triangle tiles
#define GRID_MAIN 296          // 148 SMs x 2 CTAs
#define EXK 14.4269504088896340736f   // 10 * log2(e)

__device__ float  g_zf[NN * DD];       // normalized fp32 (exact pos term)
__device__ __half g_h[NN * DD];        // normalized fp16 [n][k]
__device__ float  g_sumE[NN];          // exp-sum accumulators

__device__ __forceinline__ uint32_t smem_u32(const void* p) {
    return (uint32_t)__cvta_generic_to_shared(p);
}
__device__ __forceinline__ void cp16(uint32_t dst, const void* src) {
    asm volatile("cp.async.cg.shared.global [%0], [%1], 16;\n" :: "r"(dst), "l"(src));
}
__device__ __forceinline__ float ex2f(float x) {
    float r; asm("ex2.approx.f32 %0, %1;" : "=f"(r) : "f"(x)); return r;
}
__device__ __forceinline__ void ldsm_x4(uint32_t a, uint32_t r[4]) {
    asm volatile("ldmatrix.sync.aligned.m8n8.x4.shared.b16 {%0,%1,%2,%3}, [%4];"
                 : "=r"(r[0]), "=r"(r[1]), "=r"(r[2]), "=r"(r[3]) : "r"(a));
}
__device__ __forceinline__ void mma16816(float c[4], const uint32_t a[4],
                                         const uint32_t b[2]) {
    asm volatile(
        "mma.sync.aligned.m16n8k16.row.col.f32.f16.f16.f32 "
        "{%0,%1,%2,%3}, {%4,%5,%6,%7}, {%8,%9}, {%0,%1,%2,%3};"
        : "+f"(c[0]), "+f"(c[1]), "+f"(c[2]), "+f"(c[3])
        : "r"(a[0]), "r"(a[1]), "r"(a[2]), "r"(a[3]), "r"(b[0]), "r"(b[1]));
}

// Triangle decode: f -> (I, J), J >= I. S(I) = 64I - I(I-1)/2 tiles precede row I.
__device__ __forceinline__ void decodeIJ(int f, int& I, int& J) {
    int i = (int)((129.0f - sqrtf(16641.0f - 8.0f * (float)f)) * 0.5f);
    while (64 * (i + 1) - ((i + 1) * i) / 2 <= f) ++i;
    while (64 * i - (i * (i - 1)) / 2 > f) --i;
    I = i;
    J = i + (f - (64 * i - (i * (i - 1)) / 2));
}

// ---------------------------------------------------------------------------
// Phase 1: normalize, 2 rows per warp (ILP); zeroes g_sumE and out[0].
// ---------------------------------------------------------------------------
__global__ void __launch_bounds__(256) nt_normalize(const float* __restrict__ x,
                                                    float* __restrict__ out) {
    const int lane = threadIdx.x & 31;
    const int r0 = blockIdx.x * 8 + (threadIdx.x >> 5);   // rows r0 and r0+4096
    const int r1 = r0 + NN / 2;
    const float4 v0 = reinterpret_cast<const float4*>(x)[r0 * 32 + lane];
    const float4 v1 = reinterpret_cast<const float4*>(x)[r1 * 32 + lane];
    float s0 = v0.x * v0.x + v0.y * v0.y + v0.z * v0.z + v0.w * v0.w;
    float s1 = v1.x * v1.x + v1.y * v1.y + v1.z * v1.z + v1.w * v1.w;
#pragma unroll
    for (int o = 16; o; o >>= 1) {
        s0 += __shfl_xor_sync(0xffffffffu, s0, o);
        s1 += __shfl_xor_sync(0xffffffffu, s1, o);
    }
    const float i0 = 1.0f / fmaxf(sqrtf(s0), 1e-8f);
    const float i1 = 1.0f / fmaxf(sqrtf(s1), 1e-8f);
    float4 z0, z1;
    z0.x = v0.x * i0; z0.y = v0.y * i0; z0.z = v0.z * i0; z0.w = v0.w * i0;
    z1.x = v1.x * i1; z1.y = v1.y * i1; z1.z = v1.z * i1; z1.w = v1.w * i1;
    reinterpret_cast<float4*>(g_zf)[r0 * 32 + lane] = z0;
    reinterpret_cast<float4*>(g_zf)[r1 * 32 + lane] = z1;
    __half2* h0 = reinterpret_cast<__half2*>(g_h) + r0 * 64 + lane * 2;
    __half2* h1 = reinterpret_cast<__half2*>(g_h) + r1 * 64 + lane * 2;
    h0[0] = __floats2half2_rn(z0.x, z0.y);
    h0[1] = __floats2half2_rn(z0.z, z0.w);
    h1[0] = __floats2half2_rn(z1.x, z1.y);
    h1[1] = __floats2half2_rn(z1.z, z1.w);
    if (lane == 0) { g_sumE[r0] = 0.0f; g_sumE[r1] = 0.0f; }
    if (r0 == 0 && lane == 0) out[0] = 0.0f;
}

// Load one [128 samples][128 halves] tile into padded smem (272B rows).
__device__ __forceinline__ void load_tile(uint32_t sdst, int sbase, int tid) {
#pragma unroll
    for (int i = 0; i < 8; ++i) {          // 2048 x 16B / 256 threads
        const int f = tid + (i << 8);
        const int row = f >> 4, kb = f & 15;
        cp16(sdst + row * ROWB + (kb << 4),
             (const char*)g_h + ((size_t)(sbase + row) << 8) + (kb << 4));
    }
}

// ---------------------------------------------------------------------------
// Phase 2: chunked triangle tiles, A reused across a row, B double-buffered.
// 8 warps 2(M) x 4(N), warp tile 64x32, K=128 single pass.
// ---------------------------------------------------------------------------
__global__ void __launch_bounds__(256, 2) nt_main() {
    extern __shared__ char sm[];
    __shared__ float s_rowP[4][128];
    __shared__ float s_colP[2][128];

    const int tid = threadIdx.x, wid = tid >> 5, lane = tid & 31;
    const int wM = wid >> 2, wN = wid & 3;
    const uint32_t aBase = smem_u32(sm);
    const uint32_t bB[2] = {aBase + TILEB, aBase + 2 * TILEB};

    // chunk: 296 CTAs x (7 or 8) tiles = 2080
    const int w = blockIdx.x;
    const int cnt = 7 + (w < 8 ? 1 : 0);
    const int start = w * 7 + (w < 8 ? w : 8);

    int I, J;
    decodeIJ(start, I, J);
    load_tile(aBase, I * 128, tid);
    if (J != I) load_tile(bB[0], J * 128, tid);
    asm volatile("cp.async.commit_group;\n");
    int cur = 0;

    const uint32_t aLane = (uint32_t)((wM * 64 + (lane & 15)) * ROWB + ((lane >> 4) << 4));
    const uint32_t bLane = (uint32_t)((wN * 32 + ((lane >> 4) << 3) + (lane & 7)) * ROWB
                                      + (((lane >> 3) & 1) << 4));

    for (int k = 0; k < cnt; ++k) {
        const bool diag = (I == J);
        const int rowBase = I * 128, colBase = J * 128;
        const uint32_t bBase = diag ? aBase : bB[cur];

        asm volatile("cp.async.wait_group 0;\n" ::: "memory");
        __syncthreads();

        // next tile: (I, J+1) or row change to diag (I+1, I+1)
        const bool havenext = (k + 1 < cnt);
        const bool rowChange = havenext && (J == 63);
        const bool preB = havenext && !rowChange;       // next is off-diag, same A
        if (preB) {
            load_tile(bB[cur ^ 1], (J + 1) * 128, tid);
            asm volatile("cp.async.commit_group;\n");
        }

        float c[4][4][4];
#pragma unroll
        for (int mf = 0; mf < 4; ++mf)
#pragma unroll
            for (int nf = 0; nf < 4; ++nf)
#pragma unroll
                for (int r = 0; r < 4; ++r) c[mf][nf][r] = 0.0f;

#pragma unroll
        for (int ks = 0; ks < 8; ++ks) {
            uint32_t a[4][4], b[4][2];
#pragma unroll
            for (int mf = 0; mf < 4; ++mf)
                ldsm_x4(aBase + aLane + (uint32_t)(mf * 16 * ROWB) + (ks << 5), a[mf]);
#pragma unroll
            for (int np = 0; np < 2; ++np) {
                uint32_t r4[4];
                ldsm_x4(bBase + bLane + (uint32_t)(np * 16 * ROWB) + (ks << 5), r4);
                b[2 * np][0] = r4[0]; b[2 * np][1] = r4[1];
                b[2 * np + 1][0] = r4[2]; b[2 * np + 1][1] = r4[3];
            }
#pragma unroll
            for (int mf = 0; mf < 4; ++mf)
#pragma unroll
                for (int nf = 0; nf < 4; ++nf)
                    mma16816(c[mf][nf], a[mf], b[nf]);
        }

        // Epilogue: exp + row/col partial sums.
        const int thRow0 = rowBase + wM * 64 + (lane >> 2);
        const int thCol0 = wN * 32 + ((lane & 3) << 1);
        float sE[8], cS[8];
#pragma unroll
        for (int i = 0; i < 8; ++i) { sE[i] = 0.0f; cS[i] = 0.0f; }

        if (diag) {
#pragma unroll
            for (int mf = 0; mf < 4; ++mf)
#pragma unroll
                for (int nf = 0; nf < 4; ++nf)
#pragma unroll
                    for (int r = 0; r < 4; ++r) {
                        const int row = thRow0 + mf * 16 + ((r >> 1) << 3);
                        const int col = colBase + thCol0 + nf * 8 + (r & 1);
                        const float e = (col == row) ? 0.0f : ex2f(c[mf][nf][r] * EXK);
                        sE[mf * 2 + (r >> 1)] += e;
                    }
        } else {
#pragma unroll
            for (int mf = 0; mf < 4; ++mf)
#pragma unroll
                for (int nf = 0; nf < 4; ++nf)
#pragma unroll
                    for (int r = 0; r < 4; ++r) {
                        const float e = ex2f(c[mf][nf][r] * EXK);
                        sE[mf * 2 + (r >> 1)] += e;
                        cS[nf * 2 + (r & 1)] += e;
                    }
        }

#pragma unroll
        for (int i = 0; i < 8; ++i) {
            sE[i] += __shfl_xor_sync(0xffffffffu, sE[i], 1);
            sE[i] += __shfl_xor_sync(0xffffffffu, sE[i], 2);
        }
#pragma unroll
        for (int i = 0; i < 8; ++i) {
            cS[i] += __shfl_xor_sync(0xffffffffu, cS[i], 4);
            cS[i] += __shfl_xor_sync(0xffffffffu, cS[i], 8);
            cS[i] += __shfl_xor_sync(0xffffffffu, cS[i], 16);
        }

        if ((lane & 3) == 0) {
            const int r0 = wM * 64 + (lane >> 2);
#pragma unroll
            for (int i = 0; i < 8; ++i)
                s_rowP[wN][r0 + (i >> 1) * 16 + (i & 1) * 8] = sE[i];
        }
        if (lane < 4) {
#pragma unroll
            for (int i = 0; i < 8; ++i)
                s_colP[wM][wN * 32 + (i >> 1) * 8 + lane * 2 + (i & 1)] = cS[i];
        }
        __syncthreads();   // also: all warps done reading A (safe to reload below)

        if (tid < 128) {
            const float rs = s_rowP[0][tid] + s_rowP[1][tid]
                           + s_rowP[2][tid] + s_rowP[3][tid];
            atomicAdd(&g_sumE[rowBase + tid], rs);
            if (!diag) {
                const float cs = s_colP[0][tid] + s_colP[1][tid];
                atomicAdd(&g_sumE[colBase + tid], cs);
            }
        }

        if (rowChange) {       // next tile is (I+1, I+1): reload A only (B = A)
            load_tile(aBase, (I + 1) * 128, tid);
            asm volatile("cp.async.commit_group;\n");
            ++I; J = I;
        } else if (preB) {
            ++J; cur ^= 1;
        }
    }
}

// ---------------------------------------------------------------------------
// Phase 3: pos(i)=pos(i+4096) exact fp32, 2 pairs per warp; loss mean.
// ---------------------------------------------------------------------------
__global__ void __launch_bounds__(256) nt_final(float* __restrict__ out) {
    const int w = threadIdx.x >> 5, lane = threadIdx.x & 31;
    const int p0 = (blockIdx.x * 8 + w) * 2;          // pairs p0, p0+1 (grid 256)
    const float4 a0 = reinterpret_cast<const float4*>(g_zf)[p0 * 32 + lane];
    const float4 b0 = reinterpret_cast<const float4*>(g_zf)[(p0 + NN / 2) * 32 + lane];
    const float4 a1 = reinterpret_cast<const float4*>(g_zf)[(p0 + 1) * 32 + lane];
    const float4 b1 = reinterpret_cast<const float4*>(g_zf)[(p0 + 1 + NN / 2) * 32 + lane];
    float d0 = a0.x * b0.x + a0.y * b0.y + a0.z * b0.z + a0.w * b0.w;
    float d1 = a1.x * b1.x + a1.y * b1.y + a1.z * b1.z + a1.w * b1.w;
#pragma unroll
    for (int o = 16; o; o >>= 1) {
        d0 += __shfl_xor_sync(0xffffffffu, d0, o);
        d1 += __shfl_xor_sync(0xffffffffu, d1, o);
    }
    __shared__ float ws[8];
    if (lane == 0)
        ws[w] = __logf(g_sumE[p0]) + __logf(g_sumE[p0 + NN / 2]) - 20.0f * d0
              + __logf(g_sumE[p0 + 1]) + __logf(g_sumE[p0 + 1 + NN / 2]) - 20.0f * d1;
    __syncthreads();
    if (threadIdx.x == 0) {
        float s = 0.0f;
#pragma unroll
        for (int i = 0; i < 8; ++i) s += ws[i];
        atomicAdd(out, s * (1.0f / NN));
    }
}

// ---------------------------------------------------------------------------
extern "C" void kernel_launch(void* const* d_in, const int* in_sizes, int n_in,
                              void* d_out, int out_size) {
    (void)in_sizes; (void)n_in; (void)out_size;
    const float* x = (const float*)d_in[0];
    float* out = (float*)d_out;

    nt_normalize<<<NN / 16, 256>>>(x, out);

    const int smem = 3 * TILEB;   // 104448 B (A + 2x B)
    cudaFuncSetAttribute(nt_main, cudaFuncAttributeMaxDynamicSharedMemorySize, smem);
    nt_main<<<GRID_MAIN, 256, smem>>>();

    nt_final<<<256, 256>>>(out);
}